// round 14
// baseline (speedup 1.0000x reference)
#include <cuda_runtime.h>
#include <cuda_bf16.h>
#include <cstdint>

// TuckER via mma.sync bf16 split-precision GEMMs (sm_80 PTX, runs on Blackwell HMMA).
//   score[n] = h_bn[n]^T * R_p * W[k] * t_bn[n],  k = n>>8, p = n&255
// GEMM kernel (512 CTAs, one 128x128x128 tile each):
//   bid<256 (pass1): V[row0+c][i] = sum_j t_bn[row0+c][j] * W[k][i][j]
//   bid>=256 (pass2): G[(m<<8)+p][i] = sum_d h_bn[(m<<8)+p][d] * R_p[d][i]
// Dot kernel: out[n] = sum_i G[n][i] * V[n][i]
// fp32 -> bf16_hi + bf16_lo; D = Ah*Bh + Ah*Bl + Al*Bh (fp32 accumulate).

#define D128 128
#define NROWS 32768
#define BN_EPS 1e-5f
#define ROWB 272            // bytes per smem tile row: 128 bf16 + 8 pad

__device__ float g_V[NROWS * D128];  // 16 MB
__device__ float g_G[NROWS * D128];  // 16 MB

// dynamic smem layout (bytes)
#define SM_SCALE 0
#define SM_BIAS  512
#define SM_AHI   1024
#define SM_ALO   (SM_AHI + 128 * ROWB)
#define SM_BHI   (SM_ALO + 128 * ROWB)
#define SM_BLO   (SM_BHI + 128 * ROWB)
#define SM_TOTAL (SM_BLO + 128 * ROWB)   // 140288

__device__ __forceinline__ uint32_t smem_u32(const void* p) {
    uint32_t a;
    asm("{ .reg .u64 t; cvta.to.shared.u64 t, %1; cvt.u32.u64 %0, t; }" : "=r"(a) : "l"(p));
    return a;
}
__device__ __forceinline__ void ldm_x4(uint32_t addr, uint32_t& r0, uint32_t& r1,
                                       uint32_t& r2, uint32_t& r3) {
    asm volatile("ldmatrix.sync.aligned.m8n8.x4.shared.b16 {%0,%1,%2,%3}, [%4];"
                 : "=r"(r0), "=r"(r1), "=r"(r2), "=r"(r3) : "r"(addr));
}
__device__ __forceinline__ void ldm_x4_t(uint32_t addr, uint32_t& r0, uint32_t& r1,
                                         uint32_t& r2, uint32_t& r3) {
    asm volatile("ldmatrix.sync.aligned.m8n8.x4.trans.shared.b16 {%0,%1,%2,%3}, [%4];"
                 : "=r"(r0), "=r"(r1), "=r"(r2), "=r"(r3) : "r"(addr));
}
__device__ __forceinline__ void mma16816(float* d, uint32_t a0, uint32_t a1, uint32_t a2,
                                         uint32_t a3, uint32_t b0, uint32_t b1) {
    asm volatile("mma.sync.aligned.m16n8k16.row.col.f32.bf16.bf16.f32 "
                 "{%0,%1,%2,%3}, {%4,%5,%6,%7}, {%8,%9}, {%0,%1,%2,%3};"
                 : "+f"(d[0]), "+f"(d[1]), "+f"(d[2]), "+f"(d[3])
                 : "r"(a0), "r"(a1), "r"(a2), "r"(a3), "r"(b0), "r"(b1));
}
__device__ __forceinline__ void split2(float a, float b, uint32_t& hi, uint32_t& lo) {
    __nv_bfloat16 ah = __float2bfloat16_rn(a), bh = __float2bfloat16_rn(b);
    float ar = a - __bfloat162float(ah), br = b - __bfloat162float(bh);
    __nv_bfloat16 al = __float2bfloat16_rn(ar), bl = __float2bfloat16_rn(br);
    hi = (uint32_t)__bfloat16_as_ushort(ah) | ((uint32_t)__bfloat16_as_ushort(bh) << 16);
    lo = (uint32_t)__bfloat16_as_ushort(al) | ((uint32_t)__bfloat16_as_ushort(bl) << 16);
}

// ---------------------------------------------------------------------------
__global__ void __launch_bounds__(256, 1) tucker_gemm(
    const float* __restrict__ h, const float* __restrict__ r,
    const float* __restrict__ t, const float* __restrict__ W,
    const float* __restrict__ g0, const float* __restrict__ b0,
    const float* __restrict__ m0, const float* __restrict__ v0,
    const float* __restrict__ g1, const float* __restrict__ b1,
    const float* __restrict__ m1, const float* __restrict__ v1)
{
    extern __shared__ char smem[];
    const uint32_t sb = smem_u32(smem);
    const int tid = threadIdx.x, wid = tid >> 5, lane = tid & 31;
    const int bid = blockIdx.x;
    const bool pass1 = (bid < 256);
    const int p = bid - 256;         // pass2
    const int row0 = bid << 7;       // pass1

    float* sScale = (float*)(smem + SM_SCALE);
    float* sBias  = (float*)(smem + SM_BIAS);
    if (tid < 128) {
        float sc, bs;
        if (pass1) { sc = g1[tid] * rsqrtf(v1[tid] + BN_EPS); bs = b1[tid] - m1[tid] * sc; }
        else       { sc = g0[tid] * rsqrtf(v0[tid] + BN_EPS); bs = b0[tid] - m0[tid] * sc; }
        sScale[tid] = sc; sBias[tid] = bs;
    }
    __syncthreads();

    // ---- A tile: BN + hi/lo split, row-major [m][k] bf16 (pad ROWB) ----
    const float* Asrc = pass1 ? t : h;
#pragma unroll
    for (int it = 0; it < 16; it++) {
        int idx = tid + it * 256;
        int row = idx >> 5;                  // 0..127
        int j4  = (idx & 31) * 4;            // 0..124
        int gn  = pass1 ? (row0 + row) : ((row << 8) + p);
        float4 v  = *reinterpret_cast<const float4*>(&Asrc[(size_t)gn * D128 + j4]);
        float4 sc = *reinterpret_cast<const float4*>(&sScale[j4]);
        float4 bs = *reinterpret_cast<const float4*>(&sBias[j4]);
        uint32_t h01, l01, h23, l23;
        split2(v.x * sc.x + bs.x, v.y * sc.y + bs.y, h01, l01);
        split2(v.z * sc.z + bs.z, v.w * sc.w + bs.w, h23, l23);
        uint32_t off = (uint32_t)(row * ROWB + j4 * 2);
        *reinterpret_cast<uint2*>(smem + SM_AHI + off) = make_uint2(h01, h23);
        *reinterpret_cast<uint2*>(smem + SM_ALO + off) = make_uint2(l01, l23);
    }

    // ---- B tile: natural row-major copy + split ----
    //   pass1: W[k][i][j] -> [n=i][k=j] (col-major kxn)   -> ldmatrix
    //   pass2: R_p[d][i]  -> [k=d][n=i] (row-major kxn)   -> ldmatrix.trans
    const float* Bsrc = pass1 ? (W + (size_t)(bid >> 1) * (D128 * D128))
                              : (r + (size_t)p * (D128 * D128));
#pragma unroll
    for (int it = 0; it < 16; it++) {
        int idx = tid + it * 256;
        int row = idx >> 5;
        int j4  = (idx & 31) * 4;
        float4 v = *reinterpret_cast<const float4*>(&Bsrc[(size_t)row * D128 + j4]);
        uint32_t h01, l01, h23, l23;
        split2(v.x, v.y, h01, l01);
        split2(v.z, v.w, h23, l23);
        uint32_t off = (uint32_t)(row * ROWB + j4 * 2);
        *reinterpret_cast<uint2*>(smem + SM_BHI + off) = make_uint2(h01, h23);
        *reinterpret_cast<uint2*>(smem + SM_BLO + off) = make_uint2(l01, l23);
    }
    __syncthreads();

    // ---- mainloop: warp tile 64x32; 3 split products x 8 k16 steps ----
    const int wy = wid >> 2, wx = wid & 3;
    const int m0c = wy * 64, n0c = wx * 32;
    float acc[4][4][4];
#pragma unroll
    for (int mi = 0; mi < 4; mi++)
#pragma unroll
        for (int ni = 0; ni < 4; ni++)
#pragma unroll
            for (int q = 0; q < 4; q++) acc[mi][ni][q] = 0.0f;

    const uint32_t aB[2] = {sb + SM_AHI, sb + SM_ALO};
    const uint32_t bBs[2] = {sb + SM_BHI, sb + SM_BLO};
    const int segA[3] = {0, 0, 1}, segB[3] = {0, 1, 0};

    const int q3 = lane >> 3;                 // matrix index 0..3
    const int r7 = lane & 7;

#pragma unroll
    for (int s = 0; s < 3; s++) {
        uint32_t aBase = aB[segA[s]], bBase = bBs[segB[s]];
#pragma unroll
        for (int k16 = 0; k16 < 8; k16++) {
            int k0 = k16 * 16;
            uint32_t b[2][4];
#pragma unroll
            for (int ni2 = 0; ni2 < 2; ni2++) {
                if (pass1) {
                    int rown = n0c + ni2 * 16 + (q3 >> 1) * 8 + r7;
                    int colk = k0 + (q3 & 1) * 8;
                    ldm_x4(bBase + rown * ROWB + colk * 2,
                           b[ni2][0], b[ni2][1], b[ni2][2], b[ni2][3]);
                } else {
                    int rowk = k0 + (q3 & 1) * 8 + r7;
                    int coln = n0c + ni2 * 16 + (q3 >> 1) * 8;
                    ldm_x4_t(bBase + rowk * ROWB + coln * 2,
                             b[ni2][0], b[ni2][1], b[ni2][2], b[ni2][3]);
                }
            }
#pragma unroll
            for (int mi = 0; mi < 4; mi++) {
                uint32_t a0, a1, a2, a3;
                int rowm = m0c + mi * 16 + (lane & 15);
                int colk = k0 + (lane >> 4) * 8;
                ldm_x4(aBase + rowm * ROWB + colk * 2, a0, a1, a2, a3);
#pragma unroll
                for (int ni = 0; ni < 4; ni++)
                    mma16816(acc[mi][ni], a0, a1, a2, a3,
                             b[ni >> 1][(ni & 1) * 2], b[ni >> 1][(ni & 1) * 2 + 1]);
            }
        }
    }

    // ---- epilogue: direct STG.64; 4-lane groups fill 32B sectors ----
    float* dst = pass1 ? g_V : g_G;
    const int rsub = lane >> 2, csub = (lane & 3) * 2;
#pragma unroll
    for (int mi = 0; mi < 4; mi++) {
        int mrow = m0c + mi * 16 + rsub;
        int n1 = pass1 ? (row0 + mrow) : ((mrow << 8) + p);
        int n2 = pass1 ? (n1 + 8) : (((mrow + 8) << 8) + p);
#pragma unroll
        for (int ni = 0; ni < 4; ni++) {
            int gc = n0c + ni * 8 + csub;
            *reinterpret_cast<float2*>(&dst[(size_t)n1 * D128 + gc]) =
                make_float2(acc[mi][ni][0], acc[mi][ni][1]);
            *reinterpret_cast<float2*>(&dst[(size_t)n2 * D128 + gc]) =
                make_float2(acc[mi][ni][2], acc[mi][ni][3]);
        }
    }
}

// ---------------------------------------------------------------------------
// out[n] = sum_i g_G[n][i] * g_V[n][i]  — one warp per row (32768 warps)
// ---------------------------------------------------------------------------
__global__ void __launch_bounds__(256) tucker_dot(float* __restrict__ out)
{
    int gw  = (blockIdx.x * 256 + threadIdx.x) >> 5;
    int lid = threadIdx.x & 31;
    float4 x = *reinterpret_cast<const float4*>(&g_V[(size_t)gw * D128 + lid * 4]);
    float4 y = *reinterpret_cast<const float4*>(&g_G[(size_t)gw * D128 + lid * 4]);
    float s = x.x * y.x + x.y * y.y + x.z * y.z + x.w * y.w;
#pragma unroll
    for (int off = 16; off > 0; off >>= 1) s += __shfl_xor_sync(0xFFFFFFFFu, s, off);
    if (lid == 0) out[gw] = s;
}

// ---------------------------------------------------------------------------
// Inputs (metadata order): 0 h, 1 r, 2 t, 3 W, 4 gamma0, 5 beta0, 6 mean0,
//                          7 var0, 8 gamma1, 9 beta1, 10 mean1, 11 var1
// ---------------------------------------------------------------------------
extern "C" void kernel_launch(void* const* d_in, const int* in_sizes, int n_in,
                              void* d_out, int out_size)
{
    const float* h  = (const float*)d_in[0];
    const float* r  = (const float*)d_in[1];
    const float* t  = (const float*)d_in[2];
    const float* W  = (const float*)d_in[3];
    const float* g0 = (const float*)d_in[4];
    const float* b0 = (const float*)d_in[5];
    const float* m0 = (const float*)d_in[6];
    const float* v0 = (const float*)d_in[7];
    const float* g1 = (const float*)d_in[8];
    const float* b1 = (const float*)d_in[9];
    const float* m1 = (const float*)d_in[10];
    const float* v1 = (const float*)d_in[11];
    float* out = (float*)d_out;

    static int configured = 0;
    if (!configured) {
        cudaFuncSetAttribute(tucker_gemm, cudaFuncAttributeMaxDynamicSharedMemorySize, SM_TOTAL);
        configured = 1;
    }
    tucker_gemm<<<512, 256, SM_TOTAL>>>(h, r, t, W, g0, b0, m0, v0, g1, b1, m1, v1);
    tucker_dot<<<4096, 256>>>(out);
}

// round 15
// speedup vs baseline: 1.1654x; 1.1654x over previous
#include <cuda_runtime.h>
#include <cuda_bf16.h>
#include <cstdint>

// TuckER via mma.sync bf16 split-precision GEMMs (sm_80 PTX on Blackwell HMMA).
//   score[n] = h_bn[n]^T * R_p * W[k] * t_bn[n],  k = n>>8, p = n&255
// Kernel 1 (256 CTAs): V[row0+c][i] = sum_j t_bn[row0+c][j] * W[k][i][j]
// Kernel 2 (256 CTAs): G[kk][i] = sum_d h_bn[(kk<<8)+p][d] * R_p[d][i],
//                      out[(kk<<8)+p] = sum_i G[kk][i] * V[(kk<<8)+p][i]  (fused)
// fp32 -> bf16_hi + bf16_lo; D = Ah*Bh + Ah*Bl + Al*Bh (fp32 accumulate).

#define D128 128
#define NROWS 32768
#define BN_EPS 1e-5f
#define ROWB 272            // bytes per smem tile row: 128 bf16 + 8 pad

__device__ float g_V[NROWS * D128];  // 16 MB scratch

// dynamic smem layout (bytes)
#define SM_SCALE 0
#define SM_BIAS  512
#define SM_AHI   1024
#define SM_ALO   (SM_AHI + 128 * ROWB)
#define SM_BHI   (SM_ALO + 128 * ROWB)
#define SM_BLO   (SM_BHI + 128 * ROWB)
#define SM_TOTAL (SM_BLO + 128 * ROWB)   // 140288

__device__ __forceinline__ uint32_t smem_u32(const void* p) {
    uint32_t a;
    asm("{ .reg .u64 t; cvta.to.shared.u64 t, %1; cvt.u32.u64 %0, t; }" : "=r"(a) : "l"(p));
    return a;
}
__device__ __forceinline__ void ldm_x4(uint32_t addr, uint32_t* r) {
    asm volatile("ldmatrix.sync.aligned.m8n8.x4.shared.b16 {%0,%1,%2,%3}, [%4];"
                 : "=r"(r[0]), "=r"(r[1]), "=r"(r[2]), "=r"(r[3]) : "r"(addr));
}
__device__ __forceinline__ void ldm_x4_t(uint32_t addr, uint32_t* r) {
    asm volatile("ldmatrix.sync.aligned.m8n8.x4.trans.shared.b16 {%0,%1,%2,%3}, [%4];"
                 : "=r"(r[0]), "=r"(r[1]), "=r"(r[2]), "=r"(r[3]) : "r"(addr));
}
__device__ __forceinline__ void mma16816(float* d, const uint32_t* a, uint32_t b0, uint32_t b1) {
    asm volatile("mma.sync.aligned.m16n8k16.row.col.f32.bf16.bf16.f32 "
                 "{%0,%1,%2,%3}, {%4,%5,%6,%7}, {%8,%9}, {%0,%1,%2,%3};"
                 : "+f"(d[0]), "+f"(d[1]), "+f"(d[2]), "+f"(d[3])
                 : "r"(a[0]), "r"(a[1]), "r"(a[2]), "r"(a[3]), "r"(b0), "r"(b1));
}
__device__ __forceinline__ void split2(float a, float b, uint32_t& hi, uint32_t& lo) {
    __nv_bfloat16 ah = __float2bfloat16_rn(a), bh = __float2bfloat16_rn(b);
    float ar = a - __bfloat162float(ah), br = b - __bfloat162float(bh);
    __nv_bfloat16 al = __float2bfloat16_rn(ar), bl = __float2bfloat16_rn(br);
    hi = (uint32_t)__bfloat16_as_ushort(ah) | ((uint32_t)__bfloat16_as_ushort(bh) << 16);
    lo = (uint32_t)__bfloat16_as_ushort(al) | ((uint32_t)__bfloat16_as_ushort(bl) << 16);
}

// ===========================================================================
// Kernel 1: pass1 -> g_V
// ===========================================================================
__global__ void __launch_bounds__(256, 1) tucker_pass1(
    const float* __restrict__ t, const float* __restrict__ W,
    const float* __restrict__ g1, const float* __restrict__ b1,
    const float* __restrict__ m1, const float* __restrict__ v1)
{
    extern __shared__ char smem[];
    const uint32_t sb = smem_u32(smem);
    const int tid = threadIdx.x, wid = tid >> 5, lane = tid & 31;
    const int row0 = blockIdx.x << 7;

    float* sScale = (float*)(smem + SM_SCALE);
    float* sBias  = (float*)(smem + SM_BIAS);
    if (tid < 128) {
        float sc = g1[tid] * rsqrtf(v1[tid] + BN_EPS);
        sScale[tid] = sc; sBias[tid] = b1[tid] - m1[tid] * sc;
    }
    __syncthreads();

    // A tile: BN(t) + split
#pragma unroll
    for (int it = 0; it < 16; it++) {
        int idx = tid + it * 256;
        int row = idx >> 5, j4 = (idx & 31) * 4;
        float4 v  = *reinterpret_cast<const float4*>(&t[(size_t)(row0 + row) * D128 + j4]);
        float4 sc = *reinterpret_cast<const float4*>(&sScale[j4]);
        float4 bs = *reinterpret_cast<const float4*>(&sBias[j4]);
        uint32_t h01, l01, h23, l23;
        split2(v.x * sc.x + bs.x, v.y * sc.y + bs.y, h01, l01);
        split2(v.z * sc.z + bs.z, v.w * sc.w + bs.w, h23, l23);
        uint32_t off = (uint32_t)(row * ROWB + j4 * 2);
        *reinterpret_cast<uint2*>(smem + SM_AHI + off) = make_uint2(h01, h23);
        *reinterpret_cast<uint2*>(smem + SM_ALO + off) = make_uint2(l01, l23);
    }
    // B tile: W[k] rows i, K-major over j (col-major kxn -> plain ldmatrix)
    const float* Wk = W + (size_t)(blockIdx.x >> 1) * (D128 * D128);
#pragma unroll
    for (int it = 0; it < 16; it++) {
        int idx = tid + it * 256;
        int row = idx >> 5, j4 = (idx & 31) * 4;
        float4 v = *reinterpret_cast<const float4*>(&Wk[(size_t)row * D128 + j4]);
        uint32_t h01, l01, h23, l23;
        split2(v.x, v.y, h01, l01);
        split2(v.z, v.w, h23, l23);
        uint32_t off = (uint32_t)(row * ROWB + j4 * 2);
        *reinterpret_cast<uint2*>(smem + SM_BHI + off) = make_uint2(h01, h23);
        *reinterpret_cast<uint2*>(smem + SM_BLO + off) = make_uint2(l01, l23);
    }
    __syncthreads();

    const int wy = wid >> 2, wx = wid & 3;
    const int m0c = wy * 64, n0c = wx * 32;
    const int q3 = lane >> 3, r7 = lane & 7;
    float acc[4][4][4];
#pragma unroll
    for (int mi = 0; mi < 4; mi++)
#pragma unroll
        for (int ni = 0; ni < 4; ni++)
#pragma unroll
            for (int q = 0; q < 4; q++) acc[mi][ni][q] = 0.0f;

#pragma unroll
    for (int k16 = 0; k16 < 8; k16++) {
        int k0 = k16 * 16;
        uint32_t Bh[2][4], Bl[2][4], Ah[4][4], Al[4][4];
#pragma unroll
        for (int ni2 = 0; ni2 < 2; ni2++) {
            int rown = n0c + ni2 * 16 + (q3 >> 1) * 8 + r7;
            int colk = k0 + (q3 & 1) * 8;
            uint32_t off = (uint32_t)(rown * ROWB + colk * 2);
            ldm_x4(sb + SM_BHI + off, Bh[ni2]);
            ldm_x4(sb + SM_BLO + off, Bl[ni2]);
        }
#pragma unroll
        for (int mi = 0; mi < 4; mi++) {
            int rowm = m0c + mi * 16 + (lane & 15);
            int colk = k0 + (lane >> 4) * 8;
            uint32_t off = (uint32_t)(rowm * ROWB + colk * 2);
            ldm_x4(sb + SM_AHI + off, Ah[mi]);
            ldm_x4(sb + SM_ALO + off, Al[mi]);
        }
#pragma unroll
        for (int mi = 0; mi < 4; mi++)
#pragma unroll
            for (int ni = 0; ni < 4; ni++) {
                uint32_t bh0 = Bh[ni >> 1][(ni & 1) * 2], bh1 = Bh[ni >> 1][(ni & 1) * 2 + 1];
                uint32_t bl0 = Bl[ni >> 1][(ni & 1) * 2], bl1 = Bl[ni >> 1][(ni & 1) * 2 + 1];
                mma16816(acc[mi][ni], Ah[mi], bh0, bh1);
                mma16816(acc[mi][ni], Ah[mi], bl0, bl1);
                mma16816(acc[mi][ni], Al[mi], bh0, bh1);
            }
    }

    // epilogue: STG.64 to g_V
    const int rsub = lane >> 2, csub = (lane & 3) * 2;
#pragma unroll
    for (int mi = 0; mi < 4; mi++) {
        int n1 = row0 + m0c + mi * 16 + rsub;
#pragma unroll
        for (int ni = 0; ni < 4; ni++) {
            int gc = n0c + ni * 8 + csub;
            *reinterpret_cast<float2*>(&g_V[(size_t)n1 * D128 + gc]) =
                make_float2(acc[mi][ni][0], acc[mi][ni][1]);
            *reinterpret_cast<float2*>(&g_V[(size_t)(n1 + 8) * D128 + gc]) =
                make_float2(acc[mi][ni][2], acc[mi][ni][3]);
        }
    }
}

// ===========================================================================
// Kernel 2: pass2 GEMM + fused dot -> out
// ===========================================================================
__global__ void __launch_bounds__(256, 1) tucker_pass2(
    const float* __restrict__ h, const float* __restrict__ r,
    const float* __restrict__ g0, const float* __restrict__ b0,
    const float* __restrict__ m0, const float* __restrict__ v0,
    float* __restrict__ out)
{
    extern __shared__ char smem[];
    const uint32_t sb = smem_u32(smem);
    const int tid = threadIdx.x, wid = tid >> 5, lane = tid & 31;
    const int p = blockIdx.x;

    float* sScale = (float*)(smem + SM_SCALE);
    float* sBias  = (float*)(smem + SM_BIAS);
    if (tid < 128) {
        float sc = g0[tid] * rsqrtf(v0[tid] + BN_EPS);
        sScale[tid] = sc; sBias[tid] = b0[tid] - m0[tid] * sc;
    }
    __syncthreads();

    // A tile: BN(h), rows n = (row<<8)+p
#pragma unroll
    for (int it = 0; it < 16; it++) {
        int idx = tid + it * 256;
        int row = idx >> 5, j4 = (idx & 31) * 4;
        float4 v  = *reinterpret_cast<const float4*>(&h[(size_t)((row << 8) + p) * D128 + j4]);
        float4 sc = *reinterpret_cast<const float4*>(&sScale[j4]);
        float4 bs = *reinterpret_cast<const float4*>(&sBias[j4]);
        uint32_t h01, l01, h23, l23;
        split2(v.x * sc.x + bs.x, v.y * sc.y + bs.y, h01, l01);
        split2(v.z * sc.z + bs.z, v.w * sc.w + bs.w, h23, l23);
        uint32_t off = (uint32_t)(row * ROWB + j4 * 2);
        *reinterpret_cast<uint2*>(smem + SM_AHI + off) = make_uint2(h01, h23);
        *reinterpret_cast<uint2*>(smem + SM_ALO + off) = make_uint2(l01, l23);
    }
    // B tile: R_p natural [d][i] (row-major kxn -> ldmatrix.trans)
    const float* Rp = r + (size_t)p * (D128 * D128);
#pragma unroll
    for (int it = 0; it < 16; it++) {
        int idx = tid + it * 256;
        int row = idx >> 5, j4 = (idx & 31) * 4;
        float4 v = *reinterpret_cast<const float4*>(&Rp[(size_t)row * D128 + j4]);
        uint32_t h01, l01, h23, l23;
        split2(v.x, v.y, h01, l01);
        split2(v.z, v.w, h23, l23);
        uint32_t off = (uint32_t)(row * ROWB + j4 * 2);
        *reinterpret_cast<uint2*>(smem + SM_BHI + off) = make_uint2(h01, h23);
        *reinterpret_cast<uint2*>(smem + SM_BLO + off) = make_uint2(l01, l23);
    }
    __syncthreads();

    const int wy = wid >> 2, wx = wid & 3;
    const int m0c = wy * 64, n0c = wx * 32;
    const int q3 = lane >> 3, r7 = lane & 7;
    float acc[4][4][4];
#pragma unroll
    for (int mi = 0; mi < 4; mi++)
#pragma unroll
        for (int ni = 0; ni < 4; ni++)
#pragma unroll
            for (int q = 0; q < 4; q++) acc[mi][ni][q] = 0.0f;

#pragma unroll
    for (int k16 = 0; k16 < 8; k16++) {
        int k0 = k16 * 16;
        uint32_t Bh[2][4], Bl[2][4], Ah[4][4], Al[4][4];
#pragma unroll
        for (int ni2 = 0; ni2 < 2; ni2++) {
            int rowk = k0 + (q3 & 1) * 8 + r7;
            int coln = n0c + ni2 * 16 + (q3 >> 1) * 8;
            uint32_t off = (uint32_t)(rowk * ROWB + coln * 2);
            ldm_x4_t(sb + SM_BHI + off, Bh[ni2]);
            ldm_x4_t(sb + SM_BLO + off, Bl[ni2]);
        }
#pragma unroll
        for (int mi = 0; mi < 4; mi++) {
            int rowm = m0c + mi * 16 + (lane & 15);
            int colk = k0 + (lane >> 4) * 8;
            uint32_t off = (uint32_t)(rowm * ROWB + colk * 2);
            ldm_x4(sb + SM_AHI + off, Ah[mi]);
            ldm_x4(sb + SM_ALO + off, Al[mi]);
        }
#pragma unroll
        for (int mi = 0; mi < 4; mi++)
#pragma unroll
            for (int ni = 0; ni < 4; ni++) {
                uint32_t bh0 = Bh[ni >> 1][(ni & 1) * 2], bh1 = Bh[ni >> 1][(ni & 1) * 2 + 1];
                uint32_t bl0 = Bl[ni >> 1][(ni & 1) * 2], bl1 = Bl[ni >> 1][(ni & 1) * 2 + 1];
                mma16816(acc[mi][ni], Ah[mi], bh0, bh1);
                mma16816(acc[mi][ni], Ah[mi], bl0, bl1);
                mma16816(acc[mi][ni], Al[mi], bh0, bh1);
            }
    }

    // ---- fused dot epilogue: out[(kk<<8)+p] = sum_i G[kk][i] * V[(kk<<8)+p][i]
    __syncthreads();                       // tiles no longer needed; reuse smem
    float* sRed = (float*)(smem + SM_AHI); // [128][5] floats = 2560 B
    const int rsub = lane >> 2, csub = (lane & 3) * 2;

#pragma unroll
    for (int mi = 0; mi < 4; mi++) {
#pragma unroll
        for (int half = 0; half < 2; half++) {
            int mrow = m0c + mi * 16 + rsub + half * 8;
            size_t vbase = (size_t)((mrow << 8) + p) * D128;
            float s = 0.0f;
#pragma unroll
            for (int ni = 0; ni < 4; ni++) {
                int gc = n0c + ni * 8 + csub;
                float2 v = *reinterpret_cast<const float2*>(&g_V[vbase + gc]);
                s += acc[mi][ni][half * 2 + 0] * v.x + acc[mi][ni][half * 2 + 1] * v.y;
            }
            s += __shfl_xor_sync(0xFFFFFFFFu, s, 1);
            s += __shfl_xor_sync(0xFFFFFFFFu, s, 2);
            if ((lane & 3) == 0) sRed[mrow * 5 + wx] = s;
        }
    }
    __syncthreads();
    if (tid < 128) {
        float s = sRed[tid * 5 + 0] + sRed[tid * 5 + 1] + sRed[tid * 5 + 2] + sRed[tid * 5 + 3];
        out[(tid << 8) + p] = s;
    }
}

// ---------------------------------------------------------------------------
// Inputs (metadata order): 0 h, 1 r, 2 t, 3 W, 4 gamma0, 5 beta0, 6 mean0,
//                          7 var0, 8 gamma1, 9 beta1, 10 mean1, 11 var1
// ---------------------------------------------------------------------------
extern "C" void kernel_launch(void* const* d_in, const int* in_sizes, int n_in,
                              void* d_out, int out_size)
{
    const float* h  = (const float*)d_in[0];
    const float* r  = (const float*)d_in[1];
    const float* t  = (const float*)d_in[2];
    const float* W  = (const float*)d_in[3];
    const float* g0 = (const float*)d_in[4];
    const float* b0 = (const float*)d_in[5];
    const float* m0 = (const float*)d_in[6];
    const float* v0 = (const float*)d_in[7];
    const float* g1 = (const float*)d_in[8];
    const float* b1 = (const float*)d_in[9];
    const float* m1 = (const float*)d_in[10];
    const float* v1 = (const float*)d_in[11];
    float* out = (float*)d_out;

    static int configured = 0;
    if (!configured) {
        cudaFuncSetAttribute(tucker_pass1, cudaFuncAttributeMaxDynamicSharedMemorySize, SM_TOTAL);
        cudaFuncSetAttribute(tucker_pass2, cudaFuncAttributeMaxDynamicSharedMemorySize, SM_TOTAL);
        configured = 1;
    }
    tucker_pass1<<<256, 256, SM_TOTAL>>>(t, W, g1, b1, m1, v1);
    tucker_pass2<<<256, 256, SM_TOTAL>>>(h, r, g0, b0, m0, v0, out);
}